// round 9
// baseline (speedup 1.0000x reference)
#include <cuda_runtime.h>
#include <cstdint>

#define NN   1024
#define XD   128
#define HID  256
#define HP   128   // h-pairs

typedef unsigned long long u64;

// ---------------- scratch (device globals; no allocations) ----------------
__device__ float g_hxbT[HP * NN * 2];   // hx + b1, transposed, pair-interleaved [hp][n]{2}
__device__ float g_hyT [HP * NN * 2];   // hy, same layout
__device__ float g_c[NN];               // c_i = sum_h hy[i,h]*w2[h]
__device__ float g_d[NN];               // d_j = sum_h (hx[j,h]+b1[h])*w2[h]
__device__ float g_part[NN * 32];       // per (i, j-block) sum of exp(logit)
__device__ float g_diag[NN];            // T0_i = softplus(logit_ii)
__device__ int   g_ctr;

// ---------------- Kernel 1: h-projections (unchanged from R8) -------------
__global__ __launch_bounds__(128) void gemm_h(const float* __restrict__ X,
                                              const float* __restrict__ Y,
                                              const float* __restrict__ W1,
                                              const float* __restrict__ b1) {
    const int z = blockIdx.z;
    const float* A = (z == 0) ? X : Y;
    const float* W = W1 + z * XD * HID;
    float* outT    = (z == 0) ? g_hxbT : g_hyT;

    __shared__ float s_aT[XD][36];   // [k][n], 32 n used, pitch 36 (even!)
    __shared__ float s_w[64][32];    // [k-chunk][h]

    const int tid = threadIdx.x;
    const int gn0 = blockIdx.x * 32;
    const int gh0 = blockIdx.y * 32;

    #pragma unroll
    for (int r = 0; r < 8; r++) {
        int idx = tid + r * 128;
        int k4 = idx & 31, n_l = idx >> 5;
        float4 v = *(const float4*)(A + (gn0 + n_l) * XD + 4 * k4);
        s_aT[4 * k4 + 0][n_l] = v.x;
        s_aT[4 * k4 + 1][n_l] = v.y;
        s_aT[4 * k4 + 2][n_l] = v.z;
        s_aT[4 * k4 + 3][n_l] = v.w;
    }

    const int tx = tid & 15;        // 16 n-threads, 2 n each
    const int ty = tid >> 4;        // 8 h-threads, 4 h each

    float acc[4][2];
    #pragma unroll
    for (int a = 0; a < 4; a++) { acc[a][0] = 0.0f; acc[a][1] = 0.0f; }

    for (int kc = 0; kc < XD; kc += 64) {
        if (kc) __syncthreads();
        #pragma unroll
        for (int r = 0; r < 4; r++) {
            int idx = tid + r * 128;
            int h4 = idx & 7, k_l = idx >> 3;
            *(float4*)&s_w[k_l][4 * h4] =
                *(const float4*)(W + (kc + k_l) * HID + gh0 + 4 * h4);
        }
        __syncthreads();
        #pragma unroll 8
        for (int k = 0; k < 64; k++) {
            float2 a2 = *(const float2*)&s_aT[kc + k][2 * tx];
            float4 w4 = *(const float4*)&s_w[k][4 * ty];
            acc[0][0] = fmaf(w4.x, a2.x, acc[0][0]);
            acc[0][1] = fmaf(w4.x, a2.y, acc[0][1]);
            acc[1][0] = fmaf(w4.y, a2.x, acc[1][0]);
            acc[1][1] = fmaf(w4.y, a2.y, acc[1][1]);
            acc[2][0] = fmaf(w4.z, a2.x, acc[2][0]);
            acc[2][1] = fmaf(w4.z, a2.y, acc[2][1]);
            acc[3][0] = fmaf(w4.w, a2.x, acc[3][0]);
            acc[3][1] = fmaf(w4.w, a2.y, acc[3][1]);
        }
    }

    #pragma unroll
    for (int hh = 0; hh < 4; hh += 2) {
        int h = gh0 + 4 * ty + hh;
        float bb0 = 0.0f, bb1 = 0.0f;
        if (z == 0) { bb0 = b1[h]; bb1 = b1[h + 1]; }
        #pragma unroll
        for (int nn = 0; nn < 2; nn++) {
            int n = gn0 + 2 * tx + nn;
            *(float2*)&outT[((h >> 1) * NN + n) * 2] =
                make_float2(acc[hh][nn] + bb0, acc[hh + 1][nn] + bb1);
        }
    }
}

// ---------------- Kernel 2: c_i, d_j rank-1 terms (unchanged) -------------
__global__ __launch_bounds__(256) void cd_kernel(const float* __restrict__ W2) {
    __shared__ float sc[256], sd[256];
    const int tid = threadIdx.x;
    const int i = blockIdx.x * 128 + (tid & 127);
    const int half = tid >> 7;
    const float2* hy = (const float2*)g_hyT;
    const float2* hx = (const float2*)g_hxbT;
    const float2* w2 = (const float2*)W2;
    float c = 0.0f, d = 0.0f;
    const int hp0 = half * 64;
    #pragma unroll 8
    for (int hp = hp0; hp < hp0 + 64; hp++) {
        float2 w = w2[hp];
        float2 a = hy[hp * NN + i];
        float2 b = hx[hp * NN + i];
        c = fmaf(a.x, w.x, fmaf(a.y, w.y, c));
        d = fmaf(b.x, w.x, fmaf(b.y, w.y, d));
    }
    sc[tid] = c; sd[tid] = d;
    __syncthreads();
    if (tid < 128) {
        g_c[i] = sc[tid] + sc[tid + 128];
        g_d[i] = sd[tid] + sd[tid + 128];
    }
}

// ---------------- Kernel 3: N^2 pair kernel + fused final reduction -------
// logit[i,j] = 0.5*(sum_h |hy[i,h]+hxb[j,h]|*w2[h] + c_i + d_j) + b2
// lse_i = log(1024 + sum_j e^logit)
// Tile 32i x 32j, 256 thr (8 warps x 4 i-rows, lane -> 1 j). Pure scalar
// FADD + FFMA(|z|). Grid 32x32 = 1024 blocks (tail ~1%).
__global__ __launch_bounds__(256, 4) void pair_kernel(const float* __restrict__ W2,
                                                      const float* __restrict__ b2,
                                                      float* __restrict__ out) {
    __shared__ float s_a[32][36];   // [i][h-chunk 32], pitch 144B
    __shared__ float s_b[32][36];   // [j][h-chunk 32]
    __shared__ float s_w[HID];
    __shared__ bool  s_last;
    __shared__ float s_red[16];

    const int tid  = threadIdx.x;
    const int lane = tid & 31, w = tid >> 5;   // 8 warps; warp -> 4 i rows
    const int i0 = blockIdx.y * 32;
    const int j0 = blockIdx.x * 32;
    const u64* hyp = (const u64*)g_hyT;
    const u64* hxp = (const u64*)g_hxbT;

    s_w[tid] = W2[tid];                        // 256 threads == HID

    float acc[4];
    #pragma unroll
    for (int a = 0; a < 4; a++) acc[a] = 0.0f;

    for (int ch = 0; ch < 8; ch++) {           // 32 h (16 hp) per chunk
        const int hp0 = ch * 16;
        __syncthreads();                       // covers s_w on first iter
        #pragma unroll
        for (int r = 0; r < 2; r++) {          // s_a: 32i x 16hp u64 = 512
            int idx = tid + r * 256;
            int i_l = idx & 31, hp_l = idx >> 5;
            *(u64*)&s_a[i_l][2 * hp_l] = hyp[(hp0 + hp_l) * NN + i0 + i_l];
        }
        #pragma unroll
        for (int r = 0; r < 2; r++) {          // s_b: 32j x 16hp u64 = 512
            int idx = tid + r * 256;
            int j_l = idx & 31, hp_l = idx >> 5;
            *(u64*)&s_b[j_l][2 * hp_l] = hxp[(hp0 + hp_l) * NN + j0 + j_l];
        }
        __syncthreads();

        #pragma unroll
        for (int st = 0; st < 8; st++) {       // 4 h per step
            float4 wv = *(const float4*)&s_w[ch * 32 + st * 4];
            float4 bj = *(const float4*)&s_b[lane][st * 4];
            #pragma unroll
            for (int ii = 0; ii < 4; ii++) {
                float4 av = *(const float4*)&s_a[w * 4 + ii][st * 4];
                acc[ii] = fmaf(fabsf(av.x + bj.x), wv.x, acc[ii]);
                acc[ii] = fmaf(fabsf(av.y + bj.y), wv.y, acc[ii]);
                acc[ii] = fmaf(fabsf(av.z + bj.z), wv.z, acc[ii]);
                acc[ii] = fmaf(fabsf(av.w + bj.w), wv.w, acc[ii]);
            }
        }
    }

    // ---- epilogue: per-i sum of exp over this block's 32 j's ----
    const float b2v = b2[0];
    const int gj = j0 + lane;
    const float dv = g_d[gj];
    #pragma unroll
    for (int ii = 0; ii < 4; ii++) {
        const int gi = i0 + w * 4 + ii;
        float logit = 0.5f * (acc[ii] + g_c[gi] + dv) + b2v;
        float e = __expf(logit);
        if (gi == gj)
            g_diag[gi] = fmaxf(logit, 0.0f) + log1pf(__expf(-fabsf(logit)));
        e += __shfl_xor_sync(0xFFFFFFFFu, e, 16);
        e += __shfl_xor_sync(0xFFFFFFFFu, e, 8);
        e += __shfl_xor_sync(0xFFFFFFFFu, e, 4);
        e += __shfl_xor_sync(0xFFFFFFFFu, e, 2);
        e += __shfl_xor_sync(0xFFFFFFFFu, e, 1);
        if (lane == 0) g_part[gi * 32 + blockIdx.x] = e;
    }

    // ---- last block does the final reduction ----
    __threadfence();
    __syncthreads();
    if (tid == 0) {
        int old = atomicAdd(&g_ctr, 1);
        s_last = (old == 32 * 32 - 1);
    }
    __syncthreads();
    if (!s_last) return;
    __threadfence();

    float sumT0 = 0.0f, sumL = 0.0f;
    #pragma unroll
    for (int r = 0; r < 4; r++) {
        int i = tid * 4 + r;
        const float4* p = (const float4*)&g_part[i * 32];
        float s = 0.0f;
        #pragma unroll
        for (int q = 0; q < 8; q++) {
            float4 f = p[q];
            s += (f.x + f.y) + (f.z + f.w);
        }
        sumL  += __logf(1024.0f + s);
        sumT0 += g_diag[i];
    }
    #pragma unroll
    for (int dlt = 16; dlt >= 1; dlt >>= 1) {
        sumT0 += __shfl_xor_sync(0xFFFFFFFFu, sumT0, dlt);
        sumL  += __shfl_xor_sync(0xFFFFFFFFu, sumL,  dlt);
    }
    if (lane == 0) { s_red[w] = sumT0; s_red[8 + w] = sumL; }
    __syncthreads();
    if (tid == 0) {
        float t0 = 0.0f, l = 0.0f;
        #pragma unroll
        for (int q = 0; q < 8; q++) { t0 += s_red[q]; l += s_red[8 + q]; }
        const float invn = 1.0f / 1024.0f;
        out[0] = t0 * invn - (l * invn - logf(1024.0f));
        g_ctr = 0;
    }
}

// ---------------- launch ----------------
extern "C" void kernel_launch(void* const* d_in, const int* in_sizes, int n_in,
                              void* d_out, int out_size) {
    (void)in_sizes; (void)n_in; (void)out_size;
    const float* X  = (const float*)d_in[0];
    const float* Y  = (const float*)d_in[1];
    const float* W1 = (const float*)d_in[2];
    const float* b1 = (const float*)d_in[3];
    const float* W2 = (const float*)d_in[4];
    const float* b2 = (const float*)d_in[5];

    gemm_h   <<<dim3(32, 8, 2), 128>>>(X, Y, W1, b1);
    cd_kernel<<<8, 256>>>(W2);
    pair_kernel<<<dim3(32, 32), 256>>>(W2, b2, (float*)d_out);
}

// round 10
// speedup vs baseline: 1.1594x; 1.1594x over previous
#include <cuda_runtime.h>
#include <cstdint>

#define NN   1024
#define XD   128
#define HID  256
#define HP   128   // h-pairs

typedef unsigned long long u64;

// ---------------- scratch (device globals; no allocations) ----------------
__device__ float g_hxbT[HP * NN * 2];   // hx + b1, transposed, pair-interleaved [hp][n]{2}
__device__ float g_hyT [HP * NN * 2];   // hy, same layout
__device__ float g_c[NN];               // c_i = sum_h hy[i,h]*w2[h]
__device__ float g_d[NN];               // d_j = sum_h (hx[j,h]+b1[h])*w2[h]
__device__ float g_part[NN * 16];       // per (i, j-block) sum of exp(logit)
__device__ float g_diag[NN];            // T0_i = softplus(logit_ii)
__device__ int   g_ctr;

// ---------------- helpers ----------------
__device__ __forceinline__ void fadd2(float& r0, float& r1,
                                      float a0, float a1, float b0, float b1) {
    asm("{\n\t"
        ".reg .b64 ra, rb, rc;\n\t"
        "mov.b64 ra, {%2, %3};\n\t"
        "mov.b64 rb, {%4, %5};\n\t"
        "add.rn.f32x2 rc, ra, rb;\n\t"
        "mov.b64 {%0, %1}, rc;\n\t"
        "}" : "=f"(r0), "=f"(r1) : "f"(a0), "f"(a1), "f"(b0), "f"(b1));
}

__device__ __forceinline__ void cpa8(uint32_t dst, const void* src) {
    asm volatile("cp.async.ca.shared.global [%0], [%1], 8;\n"
                 :: "r"(dst), "l"(src));
}
__device__ __forceinline__ void cpa_commit() {
    asm volatile("cp.async.commit_group;\n" ::: "memory");
}
__device__ __forceinline__ void cpa_wait0() {
    asm volatile("cp.async.wait_group 0;\n" ::: "memory");
}

// ---------------- Kernel 1: h-projections (unchanged from R8) -------------
__global__ __launch_bounds__(128) void gemm_h(const float* __restrict__ X,
                                              const float* __restrict__ Y,
                                              const float* __restrict__ W1,
                                              const float* __restrict__ b1) {
    const int z = blockIdx.z;
    const float* A = (z == 0) ? X : Y;
    const float* W = W1 + z * XD * HID;
    float* outT    = (z == 0) ? g_hxbT : g_hyT;

    __shared__ float s_aT[XD][36];   // [k][n], 32 n used, pitch 36 (even!)
    __shared__ float s_w[64][32];    // [k-chunk][h]

    const int tid = threadIdx.x;
    const int gn0 = blockIdx.x * 32;
    const int gh0 = blockIdx.y * 32;

    #pragma unroll
    for (int r = 0; r < 8; r++) {
        int idx = tid + r * 128;
        int k4 = idx & 31, n_l = idx >> 5;
        float4 v = *(const float4*)(A + (gn0 + n_l) * XD + 4 * k4);
        s_aT[4 * k4 + 0][n_l] = v.x;
        s_aT[4 * k4 + 1][n_l] = v.y;
        s_aT[4 * k4 + 2][n_l] = v.z;
        s_aT[4 * k4 + 3][n_l] = v.w;
    }

    const int tx = tid & 15;        // 16 n-threads, 2 n each
    const int ty = tid >> 4;        // 8 h-threads, 4 h each

    float acc[4][2];
    #pragma unroll
    for (int a = 0; a < 4; a++) { acc[a][0] = 0.0f; acc[a][1] = 0.0f; }

    for (int kc = 0; kc < XD; kc += 64) {
        if (kc) __syncthreads();
        #pragma unroll
        for (int r = 0; r < 4; r++) {
            int idx = tid + r * 128;
            int h4 = idx & 7, k_l = idx >> 3;
            *(float4*)&s_w[k_l][4 * h4] =
                *(const float4*)(W + (kc + k_l) * HID + gh0 + 4 * h4);
        }
        __syncthreads();
        #pragma unroll 8
        for (int k = 0; k < 64; k++) {
            float2 a2 = *(const float2*)&s_aT[kc + k][2 * tx];
            float4 w4 = *(const float4*)&s_w[k][4 * ty];
            acc[0][0] = fmaf(w4.x, a2.x, acc[0][0]);
            acc[0][1] = fmaf(w4.x, a2.y, acc[0][1]);
            acc[1][0] = fmaf(w4.y, a2.x, acc[1][0]);
            acc[1][1] = fmaf(w4.y, a2.y, acc[1][1]);
            acc[2][0] = fmaf(w4.z, a2.x, acc[2][0]);
            acc[2][1] = fmaf(w4.z, a2.y, acc[2][1]);
            acc[3][0] = fmaf(w4.w, a2.x, acc[3][0]);
            acc[3][1] = fmaf(w4.w, a2.y, acc[3][1]);
        }
    }

    #pragma unroll
    for (int hh = 0; hh < 4; hh += 2) {
        int h = gh0 + 4 * ty + hh;
        float bb0 = 0.0f, bb1 = 0.0f;
        if (z == 0) { bb0 = b1[h]; bb1 = b1[h + 1]; }
        #pragma unroll
        for (int nn = 0; nn < 2; nn++) {
            int n = gn0 + 2 * tx + nn;
            *(float2*)&outT[((h >> 1) * NN + n) * 2] =
                make_float2(acc[hh][nn] + bb0, acc[hh + 1][nn] + bb1);
        }
    }
}

// ---------------- Kernel 2: c_i, d_j rank-1 terms (unchanged) -------------
__global__ __launch_bounds__(256) void cd_kernel(const float* __restrict__ W2) {
    __shared__ float sc[256], sd[256];
    const int tid = threadIdx.x;
    const int i = blockIdx.x * 128 + (tid & 127);
    const int half = tid >> 7;
    const float2* hy = (const float2*)g_hyT;
    const float2* hx = (const float2*)g_hxbT;
    const float2* w2 = (const float2*)W2;
    float c = 0.0f, d = 0.0f;
    const int hp0 = half * 64;
    #pragma unroll 8
    for (int hp = hp0; hp < hp0 + 64; hp++) {
        float2 w = w2[hp];
        float2 a = hy[hp * NN + i];
        float2 b = hx[hp * NN + i];
        c = fmaf(a.x, w.x, fmaf(a.y, w.y, c));
        d = fmaf(b.x, w.x, fmaf(b.y, w.y, d));
    }
    sc[tid] = c; sd[tid] = d;
    __syncthreads();
    if (tid < 128) {
        g_c[i] = sc[tid] + sc[tid + 128];
        g_d[i] = sd[tid] + sd[tid + 128];
    }
}

// ---------------- Kernel 3: N^2 pair kernel + fused final reduction -------
// logit[i,j] = 0.5*(sum_h |hy[i,h]+hxb[j,h]|*w2[h] + c_i + d_j) + b2
// lse_i = log(1024 + sum_j e^logit)
// R8 structure (32i x 64j, 256 thr, fadd2 + FFMA(|z|)) + cp.async
// double-buffered chunk fills: 1 barrier/chunk, fill latency off critical path.
__global__ __launch_bounds__(256, 4) void pair_kernel(const float* __restrict__ W2,
                                                      const float* __restrict__ b2,
                                                      float* __restrict__ out) {
    __shared__ float s_a[2][32][36];   // [buf][i][h-chunk 32]
    __shared__ float s_b[2][64][36];   // [buf][j][h-chunk 32]
    __shared__ float s_w[HID];
    __shared__ bool  s_last;
    __shared__ float s_red[16];

    const int tid  = threadIdx.x;
    const int lane = tid & 31, w = tid >> 5;   // 8 warps; warp -> 4 i rows
    const int i0 = blockIdx.y * 32;
    const int j0 = blockIdx.x * 64;
    const u64* hyp = (const u64*)g_hyT;
    const u64* hxp = (const u64*)g_hxbT;

    // per-thread fill coordinates (fixed across chunks)
    const int a0_i = tid & 31,  a0_hp = tid >> 5;            // s_a r=0
    const int a1_i = a0_i,      a1_hp = a0_hp + 8;           // s_a r=1
    const int b_j [4] = { tid & 63, tid & 63, tid & 63, tid & 63 };
    // s_b: idx = tid + r*256 -> j = idx&63 (same), hp = idx>>6
    const int b_hp0 = tid >> 6;

    uint32_t sa_base = (uint32_t)__cvta_generic_to_shared(&s_a[0][0][0]);
    uint32_t sb_base = (uint32_t)__cvta_generic_to_shared(&s_b[0][0][0]);
    const uint32_t SA_BUF = 32 * 36 * 4;   // bytes per s_a buffer
    const uint32_t SB_BUF = 64 * 36 * 4;

    s_w[tid] = W2[tid];                        // 256 threads == HID

    float acc[4][2];
    #pragma unroll
    for (int a = 0; a < 4; a++) { acc[a][0] = 0.0f; acc[a][1] = 0.0f; }

    // ---- async fill of chunk `ch` into buffer `b` ----
    auto fill = [&](int ch, int b) {
        const int hp0 = ch * 16;
        uint32_t sa = sa_base + b * SA_BUF;
        uint32_t sb = sb_base + b * SB_BUF;
        cpa8(sa + (a0_i * 36 + 2 * a0_hp) * 4, &hyp[(hp0 + a0_hp) * NN + i0 + a0_i]);
        cpa8(sa + (a1_i * 36 + 2 * a1_hp) * 4, &hyp[(hp0 + a1_hp) * NN + i0 + a1_i]);
        #pragma unroll
        for (int r = 0; r < 4; r++) {
            int hp_l = b_hp0 + r * 4;
            cpa8(sb + (b_j[r] * 36 + 2 * hp_l) * 4,
                 &hxp[(hp0 + hp_l) * NN + j0 + b_j[r]]);
        }
        cpa_commit();
    };

    fill(0, 0);
    cpa_wait0();
    __syncthreads();                           // also covers s_w

    int p = 0;
    for (int ch = 0; ch < 8; ch++) {           // 32 h (16 hp) per chunk
        if (ch < 7) fill(ch + 1, p ^ 1);

        #pragma unroll
        for (int st = 0; st < 8; st++) {       // 4 h per step
            float4 wv = *(const float4*)&s_w[ch * 32 + st * 4];
            float4 b0 = *(const float4*)&s_b[p][lane][st * 4];
            float4 b1 = *(const float4*)&s_b[p][lane + 32][st * 4];
            #pragma unroll
            for (int ii = 0; ii < 4; ii++) {
                float4 av = *(const float4*)&s_a[p][w * 4 + ii][st * 4];
                float z0, z1;
                fadd2(z0, z1, av.x, av.y, b0.x, b0.y);
                acc[ii][0] = fmaf(fabsf(z0), wv.x, acc[ii][0]);
                acc[ii][0] = fmaf(fabsf(z1), wv.y, acc[ii][0]);
                fadd2(z0, z1, av.z, av.w, b0.z, b0.w);
                acc[ii][0] = fmaf(fabsf(z0), wv.z, acc[ii][0]);
                acc[ii][0] = fmaf(fabsf(z1), wv.w, acc[ii][0]);
                fadd2(z0, z1, av.x, av.y, b1.x, b1.y);
                acc[ii][1] = fmaf(fabsf(z0), wv.x, acc[ii][1]);
                acc[ii][1] = fmaf(fabsf(z1), wv.y, acc[ii][1]);
                fadd2(z0, z1, av.z, av.w, b1.z, b1.w);
                acc[ii][1] = fmaf(fabsf(z0), wv.z, acc[ii][1]);
                acc[ii][1] = fmaf(fabsf(z1), wv.w, acc[ii][1]);
            }
        }

        if (ch < 7) {
            cpa_wait0();
            __syncthreads();
            p ^= 1;
        }
    }

    // ---- epilogue ----
    const float b2v = b2[0];
    const int gj0 = j0 + lane, gj1 = j0 + lane + 32;
    const float d0 = g_d[gj0], d1 = g_d[gj1];
    #pragma unroll
    for (int ii = 0; ii < 4; ii++) {
        const int gi = i0 + w * 4 + ii;
        const float ci = g_c[gi];
        float l0 = 0.5f * (acc[ii][0] + ci + d0) + b2v;
        float l1 = 0.5f * (acc[ii][1] + ci + d1) + b2v;
        float e = __expf(l0) + __expf(l1);
        if (gi == gj0) g_diag[gi] = fmaxf(l0, 0.0f) + log1pf(__expf(-fabsf(l0)));
        if (gi == gj1) g_diag[gi] = fmaxf(l1, 0.0f) + log1pf(__expf(-fabsf(l1)));
        e += __shfl_xor_sync(0xFFFFFFFFu, e, 16);
        e += __shfl_xor_sync(0xFFFFFFFFu, e, 8);
        e += __shfl_xor_sync(0xFFFFFFFFu, e, 4);
        e += __shfl_xor_sync(0xFFFFFFFFu, e, 2);
        e += __shfl_xor_sync(0xFFFFFFFFu, e, 1);
        if (lane == 0) g_part[gi * 16 + blockIdx.x] = e;
    }

    // ---- last block does the final reduction ----
    __threadfence();
    __syncthreads();
    if (tid == 0) {
        int old = atomicAdd(&g_ctr, 1);
        s_last = (old == 16 * 32 - 1);
    }
    __syncthreads();
    if (!s_last) return;
    __threadfence();

    float sumT0 = 0.0f, sumL = 0.0f;
    #pragma unroll
    for (int r = 0; r < 4; r++) {
        int i = tid * 4 + r;
        const float4* pp = (const float4*)&g_part[i * 16];
        float4 a = pp[0], b = pp[1], c = pp[2], d = pp[3];
        float s = ((a.x + a.y) + (a.z + a.w)) + ((b.x + b.y) + (b.z + b.w)) +
                  ((c.x + c.y) + (c.z + c.w)) + ((d.x + d.y) + (d.z + d.w));
        sumL  += __logf(1024.0f + s);
        sumT0 += g_diag[i];
    }
    #pragma unroll
    for (int dlt = 16; dlt >= 1; dlt >>= 1) {
        sumT0 += __shfl_xor_sync(0xFFFFFFFFu, sumT0, dlt);
        sumL  += __shfl_xor_sync(0xFFFFFFFFu, sumL,  dlt);
    }
    if (lane == 0) { s_red[w] = sumT0; s_red[8 + w] = sumL; }
    __syncthreads();
    if (tid == 0) {
        float t0 = 0.0f, l = 0.0f;
        #pragma unroll
        for (int q = 0; q < 8; q++) { t0 += s_red[q]; l += s_red[8 + q]; }
        const float invn = 1.0f / 1024.0f;
        out[0] = t0 * invn - (l * invn - logf(1024.0f));
        g_ctr = 0;
    }
}

// ---------------- launch ----------------
extern "C" void kernel_launch(void* const* d_in, const int* in_sizes, int n_in,
                              void* d_out, int out_size) {
    (void)in_sizes; (void)n_in; (void)out_size;
    const float* X  = (const float*)d_in[0];
    const float* Y  = (const float*)d_in[1];
    const float* W1 = (const float*)d_in[2];
    const float* b1 = (const float*)d_in[3];
    const float* W2 = (const float*)d_in[4];
    const float* b2 = (const float*)d_in[5];

    gemm_h   <<<dim3(32, 8, 2), 128>>>(X, Y, W1, b1);
    cd_kernel<<<8, 256>>>(W2);
    pair_kernel<<<dim3(16, 32), 256>>>(W2, b2, (float*)d_out);
}

// round 11
// speedup vs baseline: 1.1667x; 1.0063x over previous
#include <cuda_runtime.h>
#include <cstdint>

#define NN   1024
#define XD   128
#define HID  256
#define HP   128   // h-pairs

typedef unsigned long long u64;

// ---------------- scratch (device globals; no allocations) ----------------
__device__ float g_hxbT[HP * NN * 2];   // hx + b1, transposed, pair-interleaved [hp][n]{2}
__device__ float g_hyT [HP * NN * 2];   // hy, same layout
__device__ float g_c[NN];               // c_i = sum_h hy[i,h]*w2[h]
__device__ float g_d[NN];               // d_j = sum_h (hx[j,h]+b1[h])*w2[h]
__device__ float g_part[NN * 16];       // per (i, j-block) sum of exp(logit)
__device__ float g_diag[NN];            // T0_i = softplus(logit_ii)
__device__ int   g_ctr;

// ---------------- helpers ----------------
__device__ __forceinline__ void fadd2(float& r0, float& r1,
                                      float a0, float a1, float b0, float b1) {
    asm("{\n\t"
        ".reg .b64 ra, rb, rc;\n\t"
        "mov.b64 ra, {%2, %3};\n\t"
        "mov.b64 rb, {%4, %5};\n\t"
        "add.rn.f32x2 rc, ra, rb;\n\t"
        "mov.b64 {%0, %1}, rc;\n\t"
        "}" : "=f"(r0), "=f"(r1) : "f"(a0), "f"(a1), "f"(b0), "f"(b1));
}

__device__ __forceinline__ void cpa8(uint32_t dst, const void* src) {
    asm volatile("cp.async.ca.shared.global [%0], [%1], 8;\n"
                 :: "r"(dst), "l"(src));
}
__device__ __forceinline__ void cpa_commit() {
    asm volatile("cp.async.commit_group;\n" ::: "memory");
}
__device__ __forceinline__ void cpa_wait0() {
    asm volatile("cp.async.wait_group 0;\n" ::: "memory");
}

// ---------------- Kernel 1: h-projections (unchanged from R8) -------------
__global__ __launch_bounds__(128) void gemm_h(const float* __restrict__ X,
                                              const float* __restrict__ Y,
                                              const float* __restrict__ W1,
                                              const float* __restrict__ b1) {
    const int z = blockIdx.z;
    const float* A = (z == 0) ? X : Y;
    const float* W = W1 + z * XD * HID;
    float* outT    = (z == 0) ? g_hxbT : g_hyT;

    __shared__ float s_aT[XD][36];   // [k][n], 32 n used, pitch 36 (even!)
    __shared__ float s_w[64][32];    // [k-chunk][h]

    const int tid = threadIdx.x;
    const int gn0 = blockIdx.x * 32;
    const int gh0 = blockIdx.y * 32;

    #pragma unroll
    for (int r = 0; r < 8; r++) {
        int idx = tid + r * 128;
        int k4 = idx & 31, n_l = idx >> 5;
        float4 v = *(const float4*)(A + (gn0 + n_l) * XD + 4 * k4);
        s_aT[4 * k4 + 0][n_l] = v.x;
        s_aT[4 * k4 + 1][n_l] = v.y;
        s_aT[4 * k4 + 2][n_l] = v.z;
        s_aT[4 * k4 + 3][n_l] = v.w;
    }

    const int tx = tid & 15;        // 16 n-threads, 2 n each
    const int ty = tid >> 4;        // 8 h-threads, 4 h each

    float acc[4][2];
    #pragma unroll
    for (int a = 0; a < 4; a++) { acc[a][0] = 0.0f; acc[a][1] = 0.0f; }

    for (int kc = 0; kc < XD; kc += 64) {
        if (kc) __syncthreads();
        #pragma unroll
        for (int r = 0; r < 4; r++) {
            int idx = tid + r * 128;
            int h4 = idx & 7, k_l = idx >> 3;
            *(float4*)&s_w[k_l][4 * h4] =
                *(const float4*)(W + (kc + k_l) * HID + gh0 + 4 * h4);
        }
        __syncthreads();
        #pragma unroll 8
        for (int k = 0; k < 64; k++) {
            float2 a2 = *(const float2*)&s_aT[kc + k][2 * tx];
            float4 w4 = *(const float4*)&s_w[k][4 * ty];
            acc[0][0] = fmaf(w4.x, a2.x, acc[0][0]);
            acc[0][1] = fmaf(w4.x, a2.y, acc[0][1]);
            acc[1][0] = fmaf(w4.y, a2.x, acc[1][0]);
            acc[1][1] = fmaf(w4.y, a2.y, acc[1][1]);
            acc[2][0] = fmaf(w4.z, a2.x, acc[2][0]);
            acc[2][1] = fmaf(w4.z, a2.y, acc[2][1]);
            acc[3][0] = fmaf(w4.w, a2.x, acc[3][0]);
            acc[3][1] = fmaf(w4.w, a2.y, acc[3][1]);
        }
    }

    #pragma unroll
    for (int hh = 0; hh < 4; hh += 2) {
        int h = gh0 + 4 * ty + hh;
        float bb0 = 0.0f, bb1 = 0.0f;
        if (z == 0) { bb0 = b1[h]; bb1 = b1[h + 1]; }
        #pragma unroll
        for (int nn = 0; nn < 2; nn++) {
            int n = gn0 + 2 * tx + nn;
            *(float2*)&outT[((h >> 1) * NN + n) * 2] =
                make_float2(acc[hh][nn] + bb0, acc[hh + 1][nn] + bb1);
        }
    }
}

// ---------------- Kernel 2: c_i, d_j rank-1 terms (unchanged) -------------
__global__ __launch_bounds__(256) void cd_kernel(const float* __restrict__ W2) {
    __shared__ float sc[256], sd[256];
    const int tid = threadIdx.x;
    const int i = blockIdx.x * 128 + (tid & 127);
    const int half = tid >> 7;
    const float2* hy = (const float2*)g_hyT;
    const float2* hx = (const float2*)g_hxbT;
    const float2* w2 = (const float2*)W2;
    float c = 0.0f, d = 0.0f;
    const int hp0 = half * 64;
    #pragma unroll 8
    for (int hp = hp0; hp < hp0 + 64; hp++) {
        float2 w = w2[hp];
        float2 a = hy[hp * NN + i];
        float2 b = hx[hp * NN + i];
        c = fmaf(a.x, w.x, fmaf(a.y, w.y, c));
        d = fmaf(b.x, w.x, fmaf(b.y, w.y, d));
    }
    sc[tid] = c; sd[tid] = d;
    __syncthreads();
    if (tid < 128) {
        g_c[i] = sc[tid] + sc[tid + 128];
        g_d[i] = sd[tid] + sd[tid + 128];
    }
}

// ---------------- Kernel 3: N^2 pair kernel + fused final reduction -------
// logit[i,j] = 0.5*(sum_h |hy[i,h]+hxb[j,h]|*w2[h] + c_i + d_j) + b2
// lse_i = log(1024 + sum_j e^logit)
// Tile 16i x 64j, 128 thr (4 warps x 4 i-rows; lane -> j, j+32), cp.async
// double-buffered. Grid 64x16 = 1024 blocks, 8 blocks/SM -> ~1% imbalance.
__global__ __launch_bounds__(128, 8) void pair_kernel(const float* __restrict__ W2,
                                                      const float* __restrict__ b2,
                                                      float* __restrict__ out) {
    __shared__ float s_a[2][16][36];   // [buf][i][h-chunk 32]
    __shared__ float s_b[2][64][36];   // [buf][j][h-chunk 32]
    __shared__ float s_w[HID];
    __shared__ bool  s_last;
    __shared__ float s_red[8];

    const int tid  = threadIdx.x;
    const int lane = tid & 31, w = tid >> 5;   // 4 warps; warp -> 4 i rows
    const int i0 = blockIdx.y * 16;
    const int j0 = blockIdx.x * 64;
    const u64* hyp = (const u64*)g_hyT;
    const u64* hxp = (const u64*)g_hxbT;

    // per-thread fill coordinates (fixed across chunks)
    const int a_i = tid & 15, a_hp = tid >> 4;     // r=0: hp 0..7; r=1: +8
    const int b_j = tid & 63, b_hp = tid >> 6;     // r: hp = b_hp + 2r

    uint32_t sa_base = (uint32_t)__cvta_generic_to_shared(&s_a[0][0][0]);
    uint32_t sb_base = (uint32_t)__cvta_generic_to_shared(&s_b[0][0][0]);
    const uint32_t SA_BUF = 16 * 36 * 4;   // bytes per s_a buffer
    const uint32_t SB_BUF = 64 * 36 * 4;

    s_w[tid]       = W2[tid];
    s_w[tid + 128] = W2[tid + 128];

    float acc[4][2];
    #pragma unroll
    for (int a = 0; a < 4; a++) { acc[a][0] = 0.0f; acc[a][1] = 0.0f; }

    // ---- async fill of chunk `ch` into buffer `b` ----
    auto fill = [&](int ch, int b) {
        const int hp0 = ch * 16;
        uint32_t sa = sa_base + b * SA_BUF;
        uint32_t sb = sb_base + b * SB_BUF;
        #pragma unroll
        for (int r = 0; r < 2; r++) {
            int hp_l = a_hp + r * 8;
            cpa8(sa + (a_i * 36 + 2 * hp_l) * 4,
                 &hyp[(hp0 + hp_l) * NN + i0 + a_i]);
        }
        #pragma unroll
        for (int r = 0; r < 8; r++) {
            int hp_l = b_hp + r * 2;
            cpa8(sb + (b_j * 36 + 2 * hp_l) * 4,
                 &hxp[(hp0 + hp_l) * NN + j0 + b_j]);
        }
        cpa_commit();
    };

    fill(0, 0);
    cpa_wait0();
    __syncthreads();                           // also covers s_w

    int p = 0;
    for (int ch = 0; ch < 8; ch++) {           // 32 h (16 hp) per chunk
        if (ch < 7) fill(ch + 1, p ^ 1);

        #pragma unroll
        for (int st = 0; st < 8; st++) {       // 4 h per step
            float4 wv = *(const float4*)&s_w[ch * 32 + st * 4];
            float4 b0 = *(const float4*)&s_b[p][lane][st * 4];
            float4 b1 = *(const float4*)&s_b[p][lane + 32][st * 4];
            #pragma unroll
            for (int ii = 0; ii < 4; ii++) {
                float4 av = *(const float4*)&s_a[p][w * 4 + ii][st * 4];
                float z0, z1;
                fadd2(z0, z1, av.x, av.y, b0.x, b0.y);
                acc[ii][0] = fmaf(fabsf(z0), wv.x, acc[ii][0]);
                acc[ii][0] = fmaf(fabsf(z1), wv.y, acc[ii][0]);
                fadd2(z0, z1, av.z, av.w, b0.z, b0.w);
                acc[ii][0] = fmaf(fabsf(z0), wv.z, acc[ii][0]);
                acc[ii][0] = fmaf(fabsf(z1), wv.w, acc[ii][0]);
                fadd2(z0, z1, av.x, av.y, b1.x, b1.y);
                acc[ii][1] = fmaf(fabsf(z0), wv.x, acc[ii][1]);
                acc[ii][1] = fmaf(fabsf(z1), wv.y, acc[ii][1]);
                fadd2(z0, z1, av.z, av.w, b1.z, b1.w);
                acc[ii][1] = fmaf(fabsf(z0), wv.z, acc[ii][1]);
                acc[ii][1] = fmaf(fabsf(z1), wv.w, acc[ii][1]);
            }
        }

        if (ch < 7) {
            cpa_wait0();
            __syncthreads();
            p ^= 1;
        }
    }

    // ---- epilogue ----
    const float b2v = b2[0];
    const int gj0 = j0 + lane, gj1 = j0 + lane + 32;
    const float d0 = g_d[gj0], d1 = g_d[gj1];
    #pragma unroll
    for (int ii = 0; ii < 4; ii++) {
        const int gi = i0 + w * 4 + ii;
        const float ci = g_c[gi];
        float l0 = 0.5f * (acc[ii][0] + ci + d0) + b2v;
        float l1 = 0.5f * (acc[ii][1] + ci + d1) + b2v;
        float e = __expf(l0) + __expf(l1);
        if (gi == gj0) g_diag[gi] = fmaxf(l0, 0.0f) + log1pf(__expf(-fabsf(l0)));
        if (gi == gj1) g_diag[gi] = fmaxf(l1, 0.0f) + log1pf(__expf(-fabsf(l1)));
        e += __shfl_xor_sync(0xFFFFFFFFu, e, 16);
        e += __shfl_xor_sync(0xFFFFFFFFu, e, 8);
        e += __shfl_xor_sync(0xFFFFFFFFu, e, 4);
        e += __shfl_xor_sync(0xFFFFFFFFu, e, 2);
        e += __shfl_xor_sync(0xFFFFFFFFu, e, 1);
        if (lane == 0) g_part[gi * 16 + blockIdx.x] = e;
    }

    // ---- last block does the final reduction ----
    __threadfence();
    __syncthreads();
    if (tid == 0) {
        int old = atomicAdd(&g_ctr, 1);
        s_last = (old == 16 * 64 - 1);
    }
    __syncthreads();
    if (!s_last) return;
    __threadfence();

    float sumT0 = 0.0f, sumL = 0.0f;
    #pragma unroll
    for (int r = 0; r < 8; r++) {
        int i = tid * 8 + r;
        const float4* pp = (const float4*)&g_part[i * 16];
        float4 a = pp[0], b = pp[1], c = pp[2], d = pp[3];
        float s = ((a.x + a.y) + (a.z + a.w)) + ((b.x + b.y) + (b.z + b.w)) +
                  ((c.x + c.y) + (c.z + c.w)) + ((d.x + d.y) + (d.z + d.w));
        sumL  += __logf(1024.0f + s);
        sumT0 += g_diag[i];
    }
    #pragma unroll
    for (int dlt = 16; dlt >= 1; dlt >>= 1) {
        sumT0 += __shfl_xor_sync(0xFFFFFFFFu, sumT0, dlt);
        sumL  += __shfl_xor_sync(0xFFFFFFFFu, sumL,  dlt);
    }
    if (lane == 0) { s_red[w] = sumT0; s_red[4 + w] = sumL; }
    __syncthreads();
    if (tid == 0) {
        float t0 = (s_red[0] + s_red[1]) + (s_red[2] + s_red[3]);
        float l  = (s_red[4] + s_red[5]) + (s_red[6] + s_red[7]);
        const float invn = 1.0f / 1024.0f;
        out[0] = t0 * invn - (l * invn - logf(1024.0f));
        g_ctr = 0;
    }
}

// ---------------- launch ----------------
extern "C" void kernel_launch(void* const* d_in, const int* in_sizes, int n_in,
                              void* d_out, int out_size) {
    (void)in_sizes; (void)n_in; (void)out_size;
    const float* X  = (const float*)d_in[0];
    const float* Y  = (const float*)d_in[1];
    const float* W1 = (const float*)d_in[2];
    const float* b1 = (const float*)d_in[3];
    const float* W2 = (const float*)d_in[4];
    const float* b2 = (const float*)d_in[5];

    gemm_h   <<<dim3(32, 8, 2), 128>>>(X, Y, W1, b1);
    cd_kernel<<<8, 256>>>(W2);
    pair_kernel<<<dim3(16, 64), 128>>>(W2, b2, (float*)d_out);
}